// round 1
// baseline (speedup 1.0000x reference)
#include <cuda_runtime.h>
#include <math.h>

#define Nn 50000
#define Ee 640000
#define Dd 128
#define Hh 8
#define DHd 16
#define FFd 256
#define Cc 5
#define Ll 6
#define EPSf 1e-5f

// ---------------- scratch (device globals; no allocs allowed) ----------------
__device__ float g_x[Nn * Dd];
__device__ float g_q[Nn * Dd];
__device__ float g_k[Nn * Dd];
__device__ float g_v[Nn * Dd];
__device__ float g_attn[Nn * Dd];
__device__ float g_tmp[Nn * Dd];
__device__ float g_ff[Nn * FFd];
__device__ float g_s[Ee * Hh];
__device__ float g_smax[Nn * Hh];
__device__ float g_den[Nn * Hh];
__device__ double g_colsum[Dd];
__device__ double g_colsq[Dd];

// ---------------- small utility kernels ----------------
__global__ void copy_in_kernel(const float* __restrict__ in) {
    int i = blockIdx.x * blockDim.x + threadIdx.x;
    if (i < Nn * Dd) g_x[i] = in[i];
}

__global__ void zero_kernel(float* __restrict__ p, int n) {
    int i = blockIdx.x * blockDim.x + threadIdx.x;
    if (i < n) p[i] = 0.0f;
}

__global__ void init_nh_kernel() {
    int i = blockIdx.x * blockDim.x + threadIdx.x;
    if (i < Nn * Hh) {
        g_smax[i] = __int_as_float(0xff800000);  // -inf
        g_den[i] = 0.0f;
    }
}

// ---------------- GEMM: C[M,NC] = A[M,K] @ B[K,NC] (+bias)(+res)(relu) ----------------
// BM=128, BN=64, BK=16, 256 threads, 8x4 microtile per thread.
template <int K, int NC, bool BIAS, bool RELU, bool RES>
__global__ void gemm_kernel(const float* __restrict__ A, const float* __restrict__ B,
                            const float* __restrict__ bias, const float* __restrict__ res,
                            float* __restrict__ C) {
    const int BM = 128, BN = 64, BK = 16;
    __shared__ __align__(16) float Ast[BK][BM + 4];  // transposed A tile
    __shared__ __align__(16) float Bs[BK][BN];

    int tid = threadIdx.x;
    int tx = tid & 15;   // 0..15 (col dir, step 4)
    int ty = tid >> 4;   // 0..15 (row dir, step 8)
    int rowBase = blockIdx.x * BM;
    int colBase = blockIdx.y * BN;

    float acc[8][4];
#pragma unroll
    for (int i = 0; i < 8; i++)
#pragma unroll
        for (int j = 0; j < 4; j++) acc[i][j] = 0.0f;

    for (int kt = 0; kt < K; kt += BK) {
        // A tile: 128x16 = 512 float4, 2 per thread
#pragma unroll
        for (int l = 0; l < 2; l++) {
            int f = tid + 256 * l;
            int ar = f >> 2;           // 0..127
            int ac = (f & 3) * 4;      // 0,4,8,12
            int grow = rowBase + ar;
            float4 av = make_float4(0.f, 0.f, 0.f, 0.f);
            if (grow < Nn) av = *(const float4*)&A[grow * K + kt + ac];
            Ast[ac + 0][ar] = av.x;
            Ast[ac + 1][ar] = av.y;
            Ast[ac + 2][ar] = av.z;
            Ast[ac + 3][ar] = av.w;
        }
        // B tile: 16x64 = 256 float4, 1 per thread
        {
            int br = tid >> 4;        // 0..15
            int bc = (tid & 15) * 4;  // 0..60
            float4 bv = *(const float4*)&B[(kt + br) * NC + colBase + bc];
            *(float4*)&Bs[br][bc] = bv;
        }
        __syncthreads();
#pragma unroll
        for (int kk = 0; kk < BK; kk++) {
            float4 a0 = *(const float4*)&Ast[kk][ty * 8];
            float4 a1 = *(const float4*)&Ast[kk][ty * 8 + 4];
            float4 b4 = *(const float4*)&Bs[kk][tx * 4];
            float ar8[8] = {a0.x, a0.y, a0.z, a0.w, a1.x, a1.y, a1.z, a1.w};
            float bc4[4] = {b4.x, b4.y, b4.z, b4.w};
#pragma unroll
            for (int i = 0; i < 8; i++)
#pragma unroll
                for (int j = 0; j < 4; j++) acc[i][j] += ar8[i] * bc4[j];
        }
        __syncthreads();
    }

    int col = colBase + tx * 4;
    float b4[4] = {0.f, 0.f, 0.f, 0.f};
    if (BIAS) {
        float4 bb = *(const float4*)&bias[col];
        b4[0] = bb.x; b4[1] = bb.y; b4[2] = bb.z; b4[3] = bb.w;
    }
#pragma unroll
    for (int i = 0; i < 8; i++) {
        int row = rowBase + ty * 8 + i;
        if (row >= Nn) continue;
        float4 o;
        float* oa = &o.x;
        float r4[4] = {0.f, 0.f, 0.f, 0.f};
        if (RES) {
            float4 rr = *(const float4*)&res[row * NC + col];
            r4[0] = rr.x; r4[1] = rr.y; r4[2] = rr.z; r4[3] = rr.w;
        }
#pragma unroll
        for (int j = 0; j < 4; j++) {
            float vv = acc[i][j];
            if (BIAS) vv += b4[j];
            if (RES) vv += r4[j];
            if (RELU) vv = vv > 0.f ? vv : 0.f;
            oa[j] = vv;
        }
        *(float4*)&C[row * NC + col] = o;
    }
}

// ---------------- edge attention kernels ----------------
__global__ void score_kernel(const int* __restrict__ ei) {
    int idx = blockIdx.x * blockDim.x + threadIdx.x;
    if (idx >= Ee * Hh) return;
    int e = idx >> 3, h = idx & 7;
    int src = ei[e], dst = ei[Ee + e];
    const float4* qp = (const float4*)&g_q[dst * Dd + h * DHd];
    const float4* kp = (const float4*)&g_k[src * Dd + h * DHd];
    float s = 0.0f;
#pragma unroll
    for (int i = 0; i < 4; i++) {
        float4 qa = qp[i], ka = kp[i];
        s += qa.x * ka.x + qa.y * ka.y + qa.z * ka.z + qa.w * ka.w;
    }
    s *= 0.25f;  // 1/sqrt(16)
    g_s[idx] = s;
    float* addr = &g_smax[dst * Hh + h];
    if (s >= 0.0f)
        atomicMax((int*)addr, __float_as_int(s));
    else
        atomicMin((unsigned int*)addr, __float_as_uint(s));
}

__global__ void expden_kernel(const int* __restrict__ ei) {
    int idx = blockIdx.x * blockDim.x + threadIdx.x;
    if (idx >= Ee * Hh) return;
    int e = idx >> 3, h = idx & 7;
    int dst = ei[Ee + e];
    float sm = g_smax[dst * Hh + h];  // finite: dst has >=1 incoming edge
    float ev = expf(g_s[idx] - sm);
    g_s[idx] = ev;
    atomicAdd(&g_den[dst * Hh + h], ev);
}

__global__ void agg_kernel(const int* __restrict__ ei) {
    int idx = blockIdx.x * blockDim.x + threadIdx.x;
    if (idx >= Ee * Hh) return;
    int e = idx >> 3, h = idx & 7;
    int src = ei[e], dst = ei[Ee + e];
    float den = g_den[dst * Hh + h];
    float alpha = g_s[idx] / (den > 0.0f ? den : 1.0f);
    const float4* vp = (const float4*)&g_v[src * Dd + h * DHd];
    float* op = &g_attn[dst * Dd + h * DHd];
#pragma unroll
    for (int i = 0; i < 4; i++) {
        float4 vv = vp[i];
        atomicAdd(&op[i * 4 + 0], alpha * vv.x);
        atomicAdd(&op[i * 4 + 1], alpha * vv.y);
        atomicAdd(&op[i * 4 + 2], alpha * vv.z);
        atomicAdd(&op[i * 4 + 3], alpha * vv.w);
    }
}

// ---------------- BatchNorm ----------------
__global__ void bn_zero_kernel() {
    int t = threadIdx.x;
    if (t < Dd) {
        g_colsum[t] = 0.0;
        g_colsq[t] = 0.0;
    }
}

__global__ void bn_stats_kernel(const float* __restrict__ in) {
    int c = threadIdx.x;  // 128 threads = 128 columns
    int r0 = blockIdx.x * 128;
    int r1 = min(r0 + 128, Nn);
    float s0 = 0.f, s1 = 0.f, q0 = 0.f, q1 = 0.f;
    int r = r0;
    for (; r + 1 < r1; r += 2) {
        float a = in[r * Dd + c];
        float b = in[(r + 1) * Dd + c];
        s0 += a; q0 += a * a;
        s1 += b; q1 += b * b;
    }
    if (r < r1) {
        float a = in[r * Dd + c];
        s0 += a; q0 += a * a;
    }
    atomicAdd(&g_colsum[c], (double)(s0 + s1));
    atomicAdd(&g_colsq[c], (double)(q0 + q1));
}

__global__ void bn_apply_kernel(const float* __restrict__ in, const float* __restrict__ g,
                                const float* __restrict__ b, float* __restrict__ out) {
    int i = blockIdx.x * blockDim.x + threadIdx.x;
    if (i >= Nn * Dd) return;
    int c = i & (Dd - 1);
    double md = g_colsum[c] / (double)Nn;
    double vard = g_colsq[c] / (double)Nn - md * md;
    float m = (float)md;
    float scale = rsqrtf((float)vard + EPSf) * g[c];
    out[i] = (in[i] - m) * scale + b[c];
}

// ---------------- final projection ----------------
__global__ void proj_kernel(const float* __restrict__ Wp, const float* __restrict__ bp,
                            float* __restrict__ out) {
    int warp = blockIdx.x * (blockDim.x >> 5) + (threadIdx.x >> 5);
    int lane = threadIdx.x & 31;
    if (warp >= Nn) return;
    float acc[Cc] = {0.f, 0.f, 0.f, 0.f, 0.f};
    for (int k = lane; k < Dd; k += 32) {
        float xv = g_x[warp * Dd + k];
#pragma unroll
        for (int c = 0; c < Cc; c++) acc[c] += xv * Wp[k * Cc + c];
    }
#pragma unroll
    for (int c = 0; c < Cc; c++) {
#pragma unroll
        for (int o = 16; o > 0; o >>= 1) acc[c] += __shfl_down_sync(0xffffffffu, acc[c], o);
    }
    if (lane == 0) {
#pragma unroll
        for (int c = 0; c < Cc; c++) out[warp * Cc + c] = acc[c] + bp[c];
    }
}

// ---------------- launch ----------------
extern "C" void kernel_launch(void* const* d_in, const int* in_sizes, int n_in,
                              void* d_out, int out_size) {
    const float* x   = (const float*)d_in[0];
    const int*   ei  = (const int*)d_in[1];
    const float* Wq  = (const float*)d_in[2];
    const float* Wk  = (const float*)d_in[3];
    const float* Wv  = (const float*)d_in[4];
    const float* Wo  = (const float*)d_in[5];
    const float* g1  = (const float*)d_in[6];
    const float* bn1 = (const float*)d_in[7];
    const float* W1  = (const float*)d_in[8];
    const float* bf1 = (const float*)d_in[9];
    const float* W2  = (const float*)d_in[10];
    const float* bf2 = (const float*)d_in[11];
    const float* g2  = (const float*)d_in[12];
    const float* bn2 = (const float*)d_in[13];
    const float* Wp  = (const float*)d_in[14];
    const float* bp  = (const float*)d_in[15];
    float* out = (float*)d_out;

    float *px, *pq, *pk, *pv, *pattn, *ptmp, *pff;
    cudaGetSymbolAddress((void**)&px, g_x);
    cudaGetSymbolAddress((void**)&pq, g_q);
    cudaGetSymbolAddress((void**)&pk, g_k);
    cudaGetSymbolAddress((void**)&pv, g_v);
    cudaGetSymbolAddress((void**)&pattn, g_attn);
    cudaGetSymbolAddress((void**)&ptmp, g_tmp);
    cudaGetSymbolAddress((void**)&pff, g_ff);

    const int gemmRows = (Nn + 127) / 128;  // 391
    dim3 gD(gemmRows, Dd / 64);             // NC=128
    dim3 gF(gemmRows, FFd / 64);            // NC=256
    const int edgeBlocks = (Ee * Hh + 255) / 256;
    const int elemBlocks = (Nn * Dd + 255) / 256;
    const int nhBlocks = (Nn * Hh + 255) / 256;
    const int statBlocks = (Nn + 127) / 128;

    copy_in_kernel<<<elemBlocks, 256>>>(x);

    for (int i = 0; i < Ll; i++) {
        const float* wq = Wq + (size_t)i * Dd * Dd;
        const float* wk = Wk + (size_t)i * Dd * Dd;
        const float* wv = Wv + (size_t)i * Dd * Dd;
        const float* wo = Wo + (size_t)i * Dd * Dd;

        gemm_kernel<Dd, Dd, false, false, false><<<gD, 256>>>(px, wq, nullptr, nullptr, pq);
        gemm_kernel<Dd, Dd, false, false, false><<<gD, 256>>>(px, wk, nullptr, nullptr, pk);
        gemm_kernel<Dd, Dd, false, false, false><<<gD, 256>>>(px, wv, nullptr, nullptr, pv);

        init_nh_kernel<<<nhBlocks, 256>>>();
        score_kernel<<<edgeBlocks, 256>>>(ei);
        expden_kernel<<<edgeBlocks, 256>>>(ei);
        zero_kernel<<<elemBlocks, 256>>>(pattn, Nn * Dd);
        agg_kernel<<<edgeBlocks, 256>>>(ei);

        // tmp = attn @ Wo + x (residual)
        gemm_kernel<Dd, Dd, false, false, true><<<gD, 256>>>(pattn, wo, nullptr, px, ptmp);

        bn_zero_kernel<<<1, 128>>>();
        bn_stats_kernel<<<statBlocks, 128>>>(ptmp);
        bn_apply_kernel<<<elemBlocks, 256>>>(ptmp, g1 + i * Dd, bn1 + i * Dd, px);

        // FFN: ff = relu(x@W1 + bf1); tmp = ff@W2 + bf2 + x
        gemm_kernel<Dd, FFd, true, true, false><<<gF, 256>>>(
            px, W1 + (size_t)i * Dd * FFd, bf1 + i * FFd, nullptr, pff);
        gemm_kernel<FFd, Dd, true, false, true><<<gD, 256>>>(
            pff, W2 + (size_t)i * FFd * Dd, bf2 + i * Dd, px, ptmp);

        bn_zero_kernel<<<1, 128>>>();
        bn_stats_kernel<<<statBlocks, 128>>>(ptmp);
        bn_apply_kernel<<<elemBlocks, 256>>>(ptmp, g2 + i * Dd, bn2 + i * Dd, px);
    }

    // node_pred = x @ Wp + bp
    int projBlocks = (Nn + 7) / 8;  // 8 warps per 256-thread block
    proj_kernel<<<projBlocks, 256>>>(Wp, bp, out);
}

// round 2
// speedup vs baseline: 1.4054x; 1.4054x over previous
#include <cuda_runtime.h>
#include <math.h>

#define Nn 50000
#define Ee 640000
#define Dd 128
#define Hh 8
#define DHd 16
#define FFd 256
#define Cc 5
#define Ll 6
#define EPSf 1e-5f

#define SCAN_B 1024
#define SCAN_NB ((Nn + SCAN_B - 1) / SCAN_B)  // 49

// ---------------- scratch (device globals; no allocs allowed) ----------------
__device__ float g_x[Nn * Dd];
__device__ float g_q[Nn * Dd];
__device__ float g_k[Nn * Dd];
__device__ float g_v[Nn * Dd];
__device__ float g_attn[Nn * Dd];
__device__ float g_tmp[Nn * Dd];
__device__ float g_ff[Nn * FFd];
__device__ double g_colsum[Dd];
__device__ double g_colsq[Dd];
// CSR
__device__ int g_deg[Nn];
__device__ int g_cursor[Nn];
__device__ int g_rowptr[Nn + 1];
__device__ int g_scan[Nn];
__device__ int g_bsum[SCAN_NB];
__device__ int g_boff[SCAN_NB];
__device__ int g_col[Ee];

// ---------------- small utility kernels ----------------
__global__ void copy_in_kernel(const float* __restrict__ in) {
    int i = blockIdx.x * blockDim.x + threadIdx.x;
    if (i < Nn * Dd) g_x[i] = in[i];
}

// ---------------- CSR build ----------------
__global__ void csr_zero_kernel() {
    int i = blockIdx.x * blockDim.x + threadIdx.x;
    if (i < Nn) {
        g_deg[i] = 0;
        g_cursor[i] = 0;
    }
}

__global__ void csr_hist_kernel(const int* __restrict__ ei) {
    int e = blockIdx.x * blockDim.x + threadIdx.x;
    if (e < Ee) atomicAdd(&g_deg[ei[Ee + e]], 1);
}

__global__ void csr_scan1_kernel() {
    __shared__ int sh[SCAN_B];
    int gi = blockIdx.x * SCAN_B + threadIdx.x;
    int v = (gi < Nn) ? g_deg[gi] : 0;
    sh[threadIdx.x] = v;
    __syncthreads();
#pragma unroll
    for (int off = 1; off < SCAN_B; off <<= 1) {
        int t = (threadIdx.x >= off) ? sh[threadIdx.x - off] : 0;
        __syncthreads();
        sh[threadIdx.x] += t;
        __syncthreads();
    }
    if (gi < Nn) g_scan[gi] = sh[threadIdx.x];
    if (threadIdx.x == SCAN_B - 1) g_bsum[blockIdx.x] = sh[threadIdx.x];
}

__global__ void csr_scan2_kernel() {
    if (threadIdx.x == 0) {
        int acc = 0;
        for (int i = 0; i < SCAN_NB; i++) {
            g_boff[i] = acc;
            acc += g_bsum[i];
        }
    }
}

__global__ void csr_scan3_kernel() {
    int gi = blockIdx.x * SCAN_B + threadIdx.x;
    if (gi < Nn) g_rowptr[gi + 1] = g_scan[gi] + g_boff[blockIdx.x];
    if (gi == 0) g_rowptr[0] = 0;
}

__global__ void csr_scatter_kernel(const int* __restrict__ ei) {
    int e = blockIdx.x * blockDim.x + threadIdx.x;
    if (e >= Ee) return;
    int src = ei[e], dst = ei[Ee + e];
    int pos = g_rowptr[dst] + atomicAdd(&g_cursor[dst], 1);
    g_col[pos] = src;
}

// ---------------- GEMM: C[M,128*] = A[M,K] @ B[K,NC] ----------------
// BM=128, BN=128, BK=16, 256 threads, 8x8 microtile.
// NMAT>1: blockIdx.y selects one of up to 3 (B,C) pairs (QKV batching).
template <int K, int NC, bool BIAS, bool RELU, bool RES, int NMAT>
__global__ __launch_bounds__(256, 2) void gemm_kernel(
    const float* __restrict__ A,
    const float* __restrict__ B0, const float* __restrict__ B1, const float* __restrict__ B2,
    const float* __restrict__ bias, const float* __restrict__ res,
    float* __restrict__ C0, float* __restrict__ C1, float* __restrict__ C2) {
    const int BM = 128, BN = 128, BK = 16;
    const int YPM = NC / BN;  // y-blocks per matrix
    __shared__ __align__(16) float Ast[BK][BM + 4];
    __shared__ __align__(16) float Bs[BK][BN + 4];

    int mat = (NMAT > 1) ? (blockIdx.y / YPM) : 0;
    int colBase = (blockIdx.y % YPM) * BN;
    const float* B = (NMAT > 1) ? (mat == 0 ? B0 : (mat == 1 ? B1 : B2)) : B0;
    float* C = (NMAT > 1) ? (mat == 0 ? C0 : (mat == 1 ? C1 : C2)) : C0;

    int tid = threadIdx.x;
    int tx = tid & 15;   // col group (8 cols each)
    int ty = tid >> 4;   // row group (8 rows each)
    int rowBase = blockIdx.x * BM;

    float acc[8][8];
#pragma unroll
    for (int i = 0; i < 8; i++)
#pragma unroll
        for (int j = 0; j < 8; j++) acc[i][j] = 0.0f;

    for (int kt = 0; kt < K; kt += BK) {
        // A tile: 128x16 = 512 float4, 2 per thread (store transposed)
#pragma unroll
        for (int l = 0; l < 2; l++) {
            int f = tid + 256 * l;
            int ar = f >> 2;           // 0..127
            int ac = (f & 3) * 4;      // 0,4,8,12
            int grow = rowBase + ar;
            float4 av = make_float4(0.f, 0.f, 0.f, 0.f);
            if (grow < Nn) av = *(const float4*)&A[grow * K + kt + ac];
            Ast[ac + 0][ar] = av.x;
            Ast[ac + 1][ar] = av.y;
            Ast[ac + 2][ar] = av.z;
            Ast[ac + 3][ar] = av.w;
        }
        // B tile: 16x128 = 512 float4, 2 per thread
#pragma unroll
        for (int l = 0; l < 2; l++) {
            int f = tid + 256 * l;
            int br = f >> 5;           // 0..15
            int bc = (f & 31) * 4;     // 0..124
            float4 bv = *(const float4*)&B[(kt + br) * NC + colBase + bc];
            *(float4*)&Bs[br][bc] = bv;
        }
        __syncthreads();
#pragma unroll
        for (int kk = 0; kk < BK; kk++) {
            float4 a0 = *(const float4*)&Ast[kk][ty * 8];
            float4 a1 = *(const float4*)&Ast[kk][ty * 8 + 4];
            float4 b0 = *(const float4*)&Bs[kk][tx * 8];
            float4 b1 = *(const float4*)&Bs[kk][tx * 8 + 4];
            float ar8[8] = {a0.x, a0.y, a0.z, a0.w, a1.x, a1.y, a1.z, a1.w};
            float bc8[8] = {b0.x, b0.y, b0.z, b0.w, b1.x, b1.y, b1.z, b1.w};
#pragma unroll
            for (int i = 0; i < 8; i++)
#pragma unroll
                for (int j = 0; j < 8; j++) acc[i][j] += ar8[i] * bc8[j];
        }
        __syncthreads();
    }

    int col = colBase + tx * 8;
    float b8[8] = {0.f, 0.f, 0.f, 0.f, 0.f, 0.f, 0.f, 0.f};
    if (BIAS) {
        float4 ba = *(const float4*)&bias[col];
        float4 bb = *(const float4*)&bias[col + 4];
        b8[0] = ba.x; b8[1] = ba.y; b8[2] = ba.z; b8[3] = ba.w;
        b8[4] = bb.x; b8[5] = bb.y; b8[6] = bb.z; b8[7] = bb.w;
    }
#pragma unroll
    for (int i = 0; i < 8; i++) {
        int row = rowBase + ty * 8 + i;
        if (row >= Nn) continue;
        float r8[8] = {0.f, 0.f, 0.f, 0.f, 0.f, 0.f, 0.f, 0.f};
        if (RES) {
            float4 ra = *(const float4*)&res[row * NC + col];
            float4 rb = *(const float4*)&res[row * NC + col + 4];
            r8[0] = ra.x; r8[1] = ra.y; r8[2] = ra.z; r8[3] = ra.w;
            r8[4] = rb.x; r8[5] = rb.y; r8[6] = rb.z; r8[7] = rb.w;
        }
        float o[8];
#pragma unroll
        for (int j = 0; j < 8; j++) {
            float vv = acc[i][j];
            if (BIAS) vv += b8[j];
            if (RES) vv += r8[j];
            if (RELU) vv = vv > 0.f ? vv : 0.f;
            o[j] = vv;
        }
        *(float4*)&C[row * NC + col] = make_float4(o[0], o[1], o[2], o[3]);
        *(float4*)&C[row * NC + col + 4] = make_float4(o[4], o[5], o[6], o[7]);
    }
}

// ---------------- fused edge attention: one warp per dst node ----------------
// Online softmax over incoming edges; no atomics, single coalesced store.
__global__ void attn_fused_kernel() {
    int warp = blockIdx.x * (blockDim.x >> 5) + (threadIdx.x >> 5);
    int lane = threadIdx.x & 31;
    if (warp >= Nn) return;
    int dst = warp;

    // lane holds dims [4*lane, 4*lane+4); head = lane>>2 (quad-aligned)
    float4 q4 = *(const float4*)&g_q[dst * Dd + lane * 4];

    float m = -INFINITY;
    float l = 0.0f;
    float4 acc = make_float4(0.f, 0.f, 0.f, 0.f);

    int beg = g_rowptr[dst];
    int end = g_rowptr[dst + 1];
    for (int j = beg; j < end; j++) {
        int src = g_col[j];
        float4 k4 = *(const float4*)&g_k[src * Dd + lane * 4];
        float p = q4.x * k4.x + q4.y * k4.y + q4.z * k4.z + q4.w * k4.w;
        // quad reduction -> per-head score replicated across quad
        p += __shfl_xor_sync(0xffffffffu, p, 1);
        p += __shfl_xor_sync(0xffffffffu, p, 2);
        float s = p * 0.25f;  // 1/sqrt(16)

        float newm = fmaxf(m, s);
        float corr = __expf(m - newm);   // exp(-inf)=0 on first edge
        float pe = __expf(s - newm);
        float4 v4 = *(const float4*)&g_v[src * Dd + lane * 4];
        acc.x = acc.x * corr + pe * v4.x;
        acc.y = acc.y * corr + pe * v4.y;
        acc.z = acc.z * corr + pe * v4.z;
        acc.w = acc.w * corr + pe * v4.w;
        l = l * corr + pe;
        m = newm;
    }
    float inv = (l > 0.f) ? (1.0f / l) : 0.0f;
    acc.x *= inv; acc.y *= inv; acc.z *= inv; acc.w *= inv;
    *(float4*)&g_attn[dst * Dd + lane * 4] = acc;
}

// ---------------- BatchNorm ----------------
__global__ void bn_zero_kernel() {
    int t = threadIdx.x;
    if (t < Dd) {
        g_colsum[t] = 0.0;
        g_colsq[t] = 0.0;
    }
}

__global__ void bn_stats_kernel(const float* __restrict__ in) {
    int c = threadIdx.x;
    int r0 = blockIdx.x * 128;
    int r1 = min(r0 + 128, Nn);
    float s0 = 0.f, s1 = 0.f, q0 = 0.f, q1 = 0.f;
    int r = r0;
    for (; r + 1 < r1; r += 2) {
        float a = in[r * Dd + c];
        float b = in[(r + 1) * Dd + c];
        s0 += a; q0 += a * a;
        s1 += b; q1 += b * b;
    }
    if (r < r1) {
        float a = in[r * Dd + c];
        s0 += a; q0 += a * a;
    }
    atomicAdd(&g_colsum[c], (double)(s0 + s1));
    atomicAdd(&g_colsq[c], (double)(q0 + q1));
}

__global__ void bn_apply_kernel(const float* __restrict__ in, const float* __restrict__ g,
                                const float* __restrict__ b, float* __restrict__ out) {
    int i = blockIdx.x * blockDim.x + threadIdx.x;
    if (i >= Nn * Dd) return;
    int c = i & (Dd - 1);
    double md = g_colsum[c] / (double)Nn;
    double vard = g_colsq[c] / (double)Nn - md * md;
    float m = (float)md;
    float scale = rsqrtf((float)vard + EPSf) * g[c];
    out[i] = (in[i] - m) * scale + b[c];
}

// ---------------- final projection ----------------
__global__ void proj_kernel(const float* __restrict__ Wp, const float* __restrict__ bp,
                            float* __restrict__ out) {
    int warp = blockIdx.x * (blockDim.x >> 5) + (threadIdx.x >> 5);
    int lane = threadIdx.x & 31;
    if (warp >= Nn) return;
    float acc[Cc] = {0.f, 0.f, 0.f, 0.f, 0.f};
    for (int k = lane; k < Dd; k += 32) {
        float xv = g_x[warp * Dd + k];
#pragma unroll
        for (int c = 0; c < Cc; c++) acc[c] += xv * Wp[k * Cc + c];
    }
#pragma unroll
    for (int c = 0; c < Cc; c++) {
#pragma unroll
        for (int o = 16; o > 0; o >>= 1) acc[c] += __shfl_down_sync(0xffffffffu, acc[c], o);
    }
    if (lane == 0) {
#pragma unroll
        for (int c = 0; c < Cc; c++) out[warp * Cc + c] = acc[c] + bp[c];
    }
}

// ---------------- launch ----------------
extern "C" void kernel_launch(void* const* d_in, const int* in_sizes, int n_in,
                              void* d_out, int out_size) {
    const float* x   = (const float*)d_in[0];
    const int*   ei  = (const int*)d_in[1];
    const float* Wq  = (const float*)d_in[2];
    const float* Wk  = (const float*)d_in[3];
    const float* Wv  = (const float*)d_in[4];
    const float* Wo  = (const float*)d_in[5];
    const float* g1  = (const float*)d_in[6];
    const float* bn1 = (const float*)d_in[7];
    const float* W1  = (const float*)d_in[8];
    const float* bf1 = (const float*)d_in[9];
    const float* W2  = (const float*)d_in[10];
    const float* bf2 = (const float*)d_in[11];
    const float* g2  = (const float*)d_in[12];
    const float* bn2 = (const float*)d_in[13];
    const float* Wp  = (const float*)d_in[14];
    const float* bp  = (const float*)d_in[15];
    float* out = (float*)d_out;

    float *px, *pq, *pk, *pv, *pattn, *ptmp, *pff;
    cudaGetSymbolAddress((void**)&px, g_x);
    cudaGetSymbolAddress((void**)&pq, g_q);
    cudaGetSymbolAddress((void**)&pk, g_k);
    cudaGetSymbolAddress((void**)&pv, g_v);
    cudaGetSymbolAddress((void**)&pattn, g_attn);
    cudaGetSymbolAddress((void**)&ptmp, g_tmp);
    cudaGetSymbolAddress((void**)&pff, g_ff);

    const int gemmRows = (Nn + 127) / 128;  // 391
    const int elemBlocks = (Nn * Dd + 255) / 256;
    const int edgeBlocks = (Ee + 255) / 256;
    const int nodeBlocks = (Nn + 255) / 256;
    const int statBlocks = (Nn + 127) / 128;
    const int warpBlocks = (Nn + 7) / 8;  // 8 warps / 256-thread block

    copy_in_kernel<<<elemBlocks, 256>>>(x);

    // ---- build CSR (src lists grouped by dst) once; reused for all layers ----
    csr_zero_kernel<<<nodeBlocks, 256>>>();
    csr_hist_kernel<<<edgeBlocks, 256>>>(ei);
    csr_scan1_kernel<<<SCAN_NB, SCAN_B>>>();
    csr_scan2_kernel<<<1, 32>>>();
    csr_scan3_kernel<<<SCAN_NB, SCAN_B>>>();
    csr_scatter_kernel<<<edgeBlocks, 256>>>(ei);

    for (int i = 0; i < Ll; i++) {
        const float* wq = Wq + (size_t)i * Dd * Dd;
        const float* wk = Wk + (size_t)i * Dd * Dd;
        const float* wv = Wv + (size_t)i * Dd * Dd;
        const float* wo = Wo + (size_t)i * Dd * Dd;

        // QKV batched: grid.y = 3
        gemm_kernel<Dd, Dd, false, false, false, 3><<<dim3(gemmRows, 3), 256>>>(
            px, wq, wk, wv, nullptr, nullptr, pq, pk, pv);

        attn_fused_kernel<<<warpBlocks, 256>>>();

        // tmp = attn @ Wo + x (residual)
        gemm_kernel<Dd, Dd, false, false, true, 1><<<dim3(gemmRows, 1), 256>>>(
            pattn, wo, nullptr, nullptr, nullptr, px, ptmp, nullptr, nullptr);

        bn_zero_kernel<<<1, 128>>>();
        bn_stats_kernel<<<statBlocks, 128>>>(ptmp);
        bn_apply_kernel<<<elemBlocks, 256>>>(ptmp, g1 + i * Dd, bn1 + i * Dd, px);

        // FFN: ff = relu(x@W1 + bf1); tmp = ff@W2 + bf2 + x
        gemm_kernel<Dd, FFd, true, true, false, 1><<<dim3(gemmRows, 2), 256>>>(
            px, W1 + (size_t)i * Dd * FFd, nullptr, nullptr,
            bf1 + i * FFd, nullptr, pff, nullptr, nullptr);
        gemm_kernel<FFd, Dd, true, false, true, 1><<<dim3(gemmRows, 1), 256>>>(
            pff, W2 + (size_t)i * FFd * Dd, nullptr, nullptr,
            bf2 + i * Dd, px, ptmp, nullptr, nullptr);

        bn_zero_kernel<<<1, 128>>>();
        bn_stats_kernel<<<statBlocks, 128>>>(ptmp);
        bn_apply_kernel<<<elemBlocks, 256>>>(ptmp, g2 + i * Dd, bn2 + i * Dd, px);
    }

    // node_pred = x @ Wp + bp
    proj_kernel<<<warpBlocks, 256>>>(Wp, bp, out);
}